// round 1
// baseline (speedup 1.0000x reference)
#include <cuda_runtime.h>
#include <math.h>

// Problem constants (fixed shapes)
#define BB      4
#define NQ      900
#define DD      256
#define CH      256
#define HH      200
#define WW      200
#define HWSZ    40000
#define NHEADS  8
#define HDIM    32
#define NK      10
#define NPTS    4

// ---------------- scratch (device globals; no runtime allocation) ----------------
__device__ float g_q  [BB * NQ * DD];          // query projection (residual source)
__device__ float g_v  [BB * HWSZ * DD];        // projected BEV values (163.8 MB)
__device__ float g_off[BB * NQ * NHEADS * NPTS * 2];
__device__ float g_aw [BB * NQ * NHEADS * NPTS];
__device__ float g_s  [BB * NQ * DD];          // sampled/weighted output
__device__ float g_t  [BB * NQ * DD];          // after Wmo + residual

// ---------------- generic 128x128x8 fp32 GEMM ----------------
// C[m,n] = sum_k A(m,k) * B[k*N+n] + bias[n] (+ R[m,n] if RES)
// ATRANS=false: A(m,k) = A[m*lda + k]
// ATRANS=true : A(m,k) = A[k*lda + m]   (used for bev: (C, HW) layout)
// blockIdx.z batches with strides sA (A) / sC (C and R).
template <bool ATRANS, bool RES>
__global__ __launch_bounds__(256) void sgemm128(
    const float* __restrict__ A, const float* __restrict__ Bm,
    const float* __restrict__ bias, const float* __restrict__ Rm,
    float* __restrict__ C,
    int M, int N, int K, int lda, long sA, long sC)
{
    __shared__ float As[8][128];
    __shared__ float Bs[8][128];

    const int bm = blockIdx.y * 128;
    const int bn = blockIdx.x * 128;
    const float* Ab = A + (long)blockIdx.z * sA;
    float* Cb = C + (long)blockIdx.z * sC;

    const int tid = threadIdx.x;
    const int tx = tid & 15;       // column group (8 cols each)
    const int ty = tid >> 4;       // row group (8 rows each)

    float acc[8][8];
#pragma unroll
    for (int i = 0; i < 8; i++)
#pragma unroll
        for (int j = 0; j < 8; j++) acc[i][j] = 0.f;

    for (int k0 = 0; k0 < K; k0 += 8) {
#pragma unroll
        for (int i = 0; i < 4; i++) {
            int idx = tid + i * 256;
            if (ATRANS) {
                int kk = idx >> 7, mm = idx & 127;
                int m = bm + mm;
                As[kk][mm] = (m < M) ? Ab[(long)(k0 + kk) * lda + m] : 0.f;
            } else {
                int mm = idx >> 3, kk = idx & 7;
                int m = bm + mm;
                As[kk][mm] = (m < M) ? Ab[(long)m * lda + (k0 + kk)] : 0.f;
            }
            int kb = idx >> 7, nn = idx & 127;
            Bs[kb][nn] = Bm[(long)(k0 + kb) * N + bn + nn];
        }
        __syncthreads();

#pragma unroll
        for (int kk = 0; kk < 8; kk++) {
            float4 a0 = *(const float4*)&As[kk][ty * 8];
            float4 a1 = *(const float4*)&As[kk][ty * 8 + 4];
            float4 b0 = *(const float4*)&Bs[kk][tx * 8];
            float4 b1 = *(const float4*)&Bs[kk][tx * 8 + 4];
            float av[8] = {a0.x, a0.y, a0.z, a0.w, a1.x, a1.y, a1.z, a1.w};
            float bv_[8] = {b0.x, b0.y, b0.z, b0.w, b1.x, b1.y, b1.z, b1.w};
#pragma unroll
            for (int i = 0; i < 8; i++)
#pragma unroll
                for (int j = 0; j < 8; j++)
                    acc[i][j] = fmaf(av[i], bv_[j], acc[i][j]);
        }
        __syncthreads();
    }

    const float* Rb = RES ? (Rm + (long)blockIdx.z * sC) : (const float*)0;
#pragma unroll
    for (int i = 0; i < 8; i++) {
        int m = bm + ty * 8 + i;
        if (m >= M) continue;
#pragma unroll
        for (int j = 0; j < 8; j++) {
            int n = bn + tx * 8 + j;
            float val = acc[i][j] + bias[n];
            if (RES) val += Rb[(long)m * N + n];
            Cb[(long)m * N + n] = val;
        }
    }
}

// ---------------- offsets + attention weights (+ per-head softmax over 4 pts) ----------------
__global__ __launch_bounds__(128) void offattn_kernel(
    const float* __restrict__ Woff, const float* __restrict__ boff,
    const float* __restrict__ Wattn, const float* __restrict__ battn)
{
    __shared__ float qs[256];
    __shared__ float lg[32];
    const int row = blockIdx.x;            // b*NQ + n
    const int tid = threadIdx.x;
    const float* qr = g_q + (long)row * DD;
    qs[tid] = qr[tid];
    qs[tid + 128] = qr[tid + 128];
    __syncthreads();

    if (tid < 64) {                        // 64 offset outputs
        float s = boff[tid];
#pragma unroll 8
        for (int k = 0; k < 256; k++) s = fmaf(qs[k], Woff[k * 64 + tid], s);
        g_off[(long)row * 64 + tid] = s;
    } else if (tid < 96) {                 // 32 attention logits
        int j = tid - 64;
        float s = battn[j];
#pragma unroll 8
        for (int k = 0; k < 256; k++) s = fmaf(qs[k], Wattn[k * 32 + j], s);
        lg[j] = s;
    }
    __syncthreads();

    if (tid < 32) {
        // softmax within each head's quad (lanes 4h..4h+3)
        float x = lg[tid];
        float m = x;
        m = fmaxf(m, __shfl_xor_sync(0xffffffffu, m, 1));
        m = fmaxf(m, __shfl_xor_sync(0xffffffffu, m, 2));
        float e = expf(x - m);
        float s = e;
        s += __shfl_xor_sync(0xffffffffu, s, 1);
        s += __shfl_xor_sync(0xffffffffu, s, 2);
        g_aw[(long)row * 32 + tid] = e / s;
    }
}

// ---------------- Bezier + bilinear sampling + weighted sum ----------------
// one warp per (b, n, head); lane = channel within head (32 channels)
__global__ __launch_bounds__(128) void sample_kernel(
    const float* __restrict__ ctrl, const float* __restrict__ pc)
{
    const int gw = blockIdx.x * 4 + (threadIdx.x >> 5);   // global warp id
    const int lane = threadIdx.x & 31;
    const int h = gw & 7;
    const int bn = gw >> 3;                               // b*NQ + n
    const int b = bn / NQ;

    const float* cp = ctrl + (long)bn * 8;                // (4 points, 2)
    const float cx0 = cp[0], cy0 = cp[1], cx1 = cp[2], cy1 = cp[3];
    const float cx2 = cp[4], cy2 = cp[5], cx3 = cp[6], cy3 = cp[7];

    const float p0 = pc[0], p1 = pc[1];
    const float invx = 1.f / (pc[3] - p0);
    const float invy = 1.f / (pc[4] - p1);

    const float* offr = g_off + (long)bn * 64 + h * 8;    // (PTS,2)
    const float* awr = g_aw + (long)bn * 32 + h * 4;
    float awv[4], ox[4], oy[4];
#pragma unroll
    for (int p = 0; p < 4; p++) {
        awv[p] = awr[p];
        ox[p] = offr[p * 2];
        oy[p] = offr[p * 2 + 1];
    }

    const float* vb = g_v + (long)b * HWSZ * DD + h * HDIM + lane;
    float acc = 0.f;

#pragma unroll
    for (int k = 0; k < NK; k++) {
        float t = (float)k * (1.0f / (NK - 1));
        float u = 1.f - t;
        float b0 = u * u * u, b1 = 3.f * u * u * t, b2 = 3.f * u * t * t, b3 = t * t * t;
        float px = b0 * cx0 + b1 * cx1 + b2 * cx2 + b3 * cx3;
        float py = b0 * cy0 + b1 * cy1 + b2 * cy2 + b3 * cy3;
        float nx = fminf(fmaxf((px - p0) * invx, 0.01f), 0.99f);
        float ny = fminf(fmaxf((py - p1) * invy, 0.01f), 0.99f);

#pragma unroll
        for (int p = 0; p < 4; p++) {
            float gx = (nx + ox[p] * (1.f / WW)) * WW - 0.5f;
            float gy = (ny + oy[p] * (1.f / HH)) * HH - 0.5f;
            float fx = floorf(gx), fy = floorf(gy);
            float wx = gx - fx, wy = gy - fy;
            int xi = (int)fx, yi = (int)fy;
            float ap = awv[p];
#pragma unroll
            for (int c = 0; c < 4; c++) {
                int dx = c & 1, dy = c >> 1;
                int ix = xi + dx, iy = yi + dy;
                if (ix >= 0 && ix < WW && iy >= 0 && iy < HH) {
                    float wgt = ap * (dx ? wx : 1.f - wx) * (dy ? wy : 1.f - wy);
                    acc = fmaf(wgt, vb[(long)(iy * WW + ix) * DD], acc);
                }
            }
        }
    }
    g_s[(long)bn * DD + h * HDIM + lane] = acc;
}

// ---------------- launch ----------------
extern "C" void kernel_launch(void* const* d_in, const int* in_sizes, int n_in,
                              void* d_out, int out_size)
{
    const float* query = (const float*)d_in[0];
    const float* ctrl  = (const float*)d_in[1];
    const float* bev   = (const float*)d_in[2];
    // d_in[3] spatial_shapes: constants (200,200), unused
    const float* pc    = (const float*)d_in[4];
    const float* Wq    = (const float*)d_in[5];
    const float* bq    = (const float*)d_in[6];
    const float* Wv    = (const float*)d_in[7];
    const float* bv    = (const float*)d_in[8];
    const float* Woff  = (const float*)d_in[9];
    const float* boff  = (const float*)d_in[10];
    const float* Wattn = (const float*)d_in[11];
    const float* battn = (const float*)d_in[12];
    const float* Wmo   = (const float*)d_in[13];
    const float* bmo   = (const float*)d_in[14];
    const float* Wo    = (const float*)d_in[15];
    const float* bo    = (const float*)d_in[16];
    float* out = (float*)d_out;

    float *pq, *pv, *ps, *pt;
    cudaGetSymbolAddress((void**)&pq, g_q);
    cudaGetSymbolAddress((void**)&pv, g_v);
    cudaGetSymbolAddress((void**)&ps, g_s);
    cudaGetSymbolAddress((void**)&pt, g_t);

    const int Mq = BB * NQ;                          // 3600
    // q = query @ Wq + bq
    sgemm128<false, false><<<dim3(2, (Mq + 127) / 128, 1), 256>>>(
        query, Wq, bq, nullptr, pq, Mq, DD, DD, DD, 0, 0);

    // offsets + attention weights (reads g_q)
    offattn_kernel<<<Mq, 128>>>(Woff, boff, Wattn, battn);

    // v = bev^T @ Wv + bv   (per batch)
    sgemm128<true, false><<<dim3(2, (HWSZ + 127) / 128, BB), 256>>>(
        bev, Wv, bv, nullptr, pv, HWSZ, DD, CH, HWSZ,
        (long)CH * HWSZ, (long)HWSZ * DD);

    // bezier + bilinear sampling + attention-weighted sum
    sample_kernel<<<(BB * NQ * NHEADS) / 4, 128>>>(ctrl, pc);

    // t = s @ Wmo + bmo + q
    sgemm128<false, true><<<dim3(2, (Mq + 127) / 128, 1), 256>>>(
        ps, Wmo, bmo, pq, pt, Mq, DD, DD, DD, 0, 0);

    // out = t @ Wo + bo
    sgemm128<false, false><<<dim3(2, (Mq + 127) / 128, 1), 256>>>(
        pt, Wo, bo, nullptr, out, Mq, DD, DD, DD, 0, 0);
}

// round 3
// speedup vs baseline: 1.6163x; 1.6163x over previous
#include <cuda_runtime.h>
#include <cuda_bf16.h>
#include <cstdint>
#include <math.h>

// Problem constants (fixed shapes)
#define BB      4
#define NQ      900
#define DD      256
#define CH      256
#define HH      200
#define WW      200
#define HWSZ    40000
#define NHEADS  8
#define HDIM    32
#define NK      10
#define NPTS    4

// ---------------- scratch (device globals; no runtime allocation) ----------------
__device__ float g_q  [BB * NQ * DD];
__device__ float g_v  [BB * HWSZ * DD];          // projected BEV values (fp32)
__device__ float g_off[BB * NQ * NHEADS * NPTS * 2];
__device__ float g_aw [BB * NQ * NHEADS * NPTS];
__device__ float g_s  [BB * NQ * DD];
__device__ float g_t  [BB * NQ * DD];
__device__ __nv_bfloat16 g_bhi[DD * CH];         // WvT [n][k] hi
__device__ __nv_bfloat16 g_blo[DD * CH];         // WvT [n][k] lo

// ---------------- helpers ----------------
__device__ __forceinline__ uint32_t smem_u32(const void* p) {
    uint32_t a;
    asm("{ .reg .u64 t; cvta.to.shared.u64 t, %1; cvt.u32.u64 %0, t; }" : "=r"(a) : "l"(p));
    return a;
}
__device__ __forceinline__ uint32_t bf2u(__nv_bfloat16 a, __nv_bfloat16 b) {
    __nv_bfloat162 t(a, b);          // a = low half
    return *reinterpret_cast<uint32_t*>(&t);
}

#define LDSM_T(r, addr) \
    asm volatile("ldmatrix.sync.aligned.m8n8.x4.trans.shared.b16 {%0,%1,%2,%3}, [%4];" \
        : "=r"((r)[0]), "=r"((r)[1]), "=r"((r)[2]), "=r"((r)[3]) : "r"(addr))
#define LDSM(r, addr) \
    asm volatile("ldmatrix.sync.aligned.m8n8.x4.shared.b16 {%0,%1,%2,%3}, [%4];" \
        : "=r"((r)[0]), "=r"((r)[1]), "=r"((r)[2]), "=r"((r)[3]) : "r"(addr))
#define MMA_BF16(c, a, b0, b1) \
    asm volatile("mma.sync.aligned.m16n8k16.row.col.f32.bf16.bf16.f32 " \
        "{%0,%1,%2,%3},{%4,%5,%6,%7},{%8,%9},{%0,%1,%2,%3};" \
        : "+f"((c)[0]), "+f"((c)[1]), "+f"((c)[2]), "+f"((c)[3]) \
        : "r"((a)[0]), "r"((a)[1]), "r"((a)[2]), "r"((a)[3]), "r"(b0), "r"(b1))

// ---------------- Wv (K=256, N=256) -> WvT hi/lo [n][k] ----------------
__global__ __launch_bounds__(256) void conv_wv(const float* __restrict__ Wv)
{
    int idx = blockIdx.x * 256 + threadIdx.x;   // n*256 + k
    int n = idx >> 8, k = idx & 255;
    float v = Wv[k * DD + n];
    __nv_bfloat16 hi = __float2bfloat16(v);
    g_bhi[idx] = hi;
    g_blo[idx] = __float2bfloat16(v - __bfloat162float(hi));
}

// ---------------- HMMA GEMM: v[b,m,:] = bev^T[b,m,:] @ WvT^T + bv --------------
// CTA tile 64(m) x 256(n), K=256 in chunks of 32; 3-term bf16 split, fp32 acc.
// A smem: [k 32][m 64+8pad]  (trans-ldmatrix, conflict-free)
// B smem: [n 256][k 32+8pad] (ldmatrix, conflict-free)
#define APITCH 72
#define BPITCH 40
#define A_SZ   (32 * APITCH * 2)                 // 4608 bytes per (buf,hl)
#define B_SZ   (256 * BPITCH * 2)                // 20480
#define AB(buf, hl) (((buf) * 2 + (hl)) * A_SZ)            // 0..18432
#define BBASE(buf, hl) (18432 + ((buf) * 2 + (hl)) * B_SZ) // ..100352
#define GEMM_SMEM 100352

__global__ void __launch_bounds__(256, 1) gemm_v(
    const float* __restrict__ bev, const float* __restrict__ bias)
{
    extern __shared__ char smem[];
    const uint32_t sb = smem_u32(smem);
    const int tid = threadIdx.x;
    const int wid = tid >> 5, lane = tid & 31;
    const int warp_m = wid & 1;          // 2 warps over m (32 each)
    const int warp_n = wid >> 1;         // 4 warps over n (64 each)
    const int m0 = blockIdx.x * 64;
    const int b = blockIdx.y;

    const float* Ag = bev + (long)b * CH * HWSZ + m0;     // A[k][m] rows

    // ldmatrix per-lane offsets (bytes), invariant across chunks
    const int tile = lane >> 3;
    const int kl = (lane & 7) + ((tile & 2) << 2);        // k row within 16
    uint32_t aoff[2];
#pragma unroll
    for (int mf = 0; mf < 2; mf++) {
        int mcol = warp_m * 32 + mf * 16 + ((tile & 1) << 3);
        aoff[mf] = (uint32_t)(kl * APITCH + mcol) * 2;
    }
    uint32_t boff[4];
#pragma unroll
    for (int q = 0; q < 4; q++) {
        int row = warp_n * 64 + q * 16 + ((tile & 1) << 3) + (lane & 7);
        int kcol = (tile & 2) << 2;
        boff[q] = (uint32_t)(row * BPITCH + kcol) * 2;
    }

    float acc[2][8][4];
#pragma unroll
    for (int i = 0; i < 2; i++)
#pragma unroll
        for (int j = 0; j < 8; j++)
#pragma unroll
            for (int r = 0; r < 4; r++) acc[i][j][r] = 0.f;

    float4 rA[2];
    uint4 rBh[4], rBl[4];

    auto g_load = [&](int kc) {
        const int k0 = kc * 32;
#pragma unroll
        for (int p = 0; p < 2; p++) {
            int idx = tid + p * 256;
            int k = idx >> 4, m4 = (idx & 15) << 2;
            rA[p] = *(const float4*)(Ag + (long)(k0 + k) * HWSZ + m4);
        }
#pragma unroll
        for (int p = 0; p < 4; p++) {
            int idx = tid + p * 256;
            int n = idx >> 2, c = idx & 3;
            rBh[p] = *(const uint4*)(g_bhi + n * 256 + k0 + c * 8);
            rBl[p] = *(const uint4*)(g_blo + n * 256 + k0 + c * 8);
        }
    };
    auto s_store = [&](int buf) {
#pragma unroll
        for (int p = 0; p < 2; p++) {
            int idx = tid + p * 256;
            int k = idx >> 4, m4 = (idx & 15) << 2;
            float4 v = rA[p];
            __nv_bfloat16 h0 = __float2bfloat16(v.x), h1 = __float2bfloat16(v.y);
            __nv_bfloat16 h2 = __float2bfloat16(v.z), h3 = __float2bfloat16(v.w);
            __nv_bfloat16 l0 = __float2bfloat16(v.x - __bfloat162float(h0));
            __nv_bfloat16 l1 = __float2bfloat16(v.y - __bfloat162float(h1));
            __nv_bfloat16 l2 = __float2bfloat16(v.z - __bfloat162float(h2));
            __nv_bfloat16 l3 = __float2bfloat16(v.w - __bfloat162float(h3));
            uint32_t off = (uint32_t)(k * APITCH + m4) * 2;
            *(uint2*)(smem + AB(buf, 0) + off) = make_uint2(bf2u(h0, h1), bf2u(h2, h3));
            *(uint2*)(smem + AB(buf, 1) + off) = make_uint2(bf2u(l0, l1), bf2u(l2, l3));
        }
#pragma unroll
        for (int p = 0; p < 4; p++) {
            int idx = tid + p * 256;
            int n = idx >> 2, c = idx & 3;
            uint32_t off = (uint32_t)(n * BPITCH + c * 8) * 2;
            *(uint4*)(smem + BBASE(buf, 0) + off) = rBh[p];
            *(uint4*)(smem + BBASE(buf, 1) + off) = rBl[p];
        }
    };

    g_load(0);
    s_store(0);
    __syncthreads();

    for (int kc = 0; kc < 8; kc++) {
        const int cur = kc & 1;
        if (kc < 7) g_load(kc + 1);

        const uint32_t Ah = sb + AB(cur, 0), Al = sb + AB(cur, 1);
        const uint32_t Bh = sb + BBASE(cur, 0), Bl = sb + BBASE(cur, 1);
#pragma unroll
        for (int ks = 0; ks < 2; ks++) {
            uint32_t ah[2][4], al[2][4], bh[4][4], bl[4][4];
#pragma unroll
            for (int mf = 0; mf < 2; mf++) {
                LDSM_T(ah[mf], Ah + aoff[mf] + ks * (16 * APITCH * 2));
                LDSM_T(al[mf], Al + aoff[mf] + ks * (16 * APITCH * 2));
            }
#pragma unroll
            for (int q = 0; q < 4; q++) {
                LDSM(bh[q], Bh + boff[q] + ks * 32);
                LDSM(bl[q], Bl + boff[q] + ks * 32);
            }
#pragma unroll
            for (int mf = 0; mf < 2; mf++)
#pragma unroll
                for (int nf = 0; nf < 8; nf++) {
                    int q = nf >> 1, h = nf & 1;
                    MMA_BF16(acc[mf][nf], ah[mf], bh[q][h], bh[q][h + 2]);
                    MMA_BF16(acc[mf][nf], ah[mf], bl[q][h], bl[q][h + 2]);
                    MMA_BF16(acc[mf][nf], al[mf], bh[q][h], bh[q][h + 2]);
                }
        }
        if (kc < 7) s_store(1 - cur);
        __syncthreads();
    }

    // epilogue: direct float2 stores (32B sectors per quad)
    float* vout = g_v + ((long)b * HWSZ + m0) * DD;
#pragma unroll
    for (int mf = 0; mf < 2; mf++) {
        int mrow = warp_m * 32 + mf * 16 + (lane >> 2);
#pragma unroll
        for (int nf = 0; nf < 8; nf++) {
            int n = warp_n * 64 + nf * 8 + (lane & 3) * 2;
            float2 bb = *(const float2*)(bias + n);
            float2 s0 = make_float2(acc[mf][nf][0] + bb.x, acc[mf][nf][1] + bb.y);
            float2 s1 = make_float2(acc[mf][nf][2] + bb.x, acc[mf][nf][3] + bb.y);
            *(float2*)(vout + (long)mrow * DD + n) = s0;
            *(float2*)(vout + (long)(mrow + 8) * DD + n) = s1;
        }
    }
}

// ---------------- generic 128x128x8 fp32 GEMM (small projections) ----------------
template <bool ATRANS, bool RES>
__global__ __launch_bounds__(256) void sgemm128(
    const float* __restrict__ A, const float* __restrict__ Bm,
    const float* __restrict__ bias, const float* __restrict__ Rm,
    float* __restrict__ C,
    int M, int N, int K, int lda, long sA, long sC)
{
    __shared__ float As[8][128];
    __shared__ float Bs[8][128];
    const int bm = blockIdx.y * 128;
    const int bn = blockIdx.x * 128;
    const float* Ab = A + (long)blockIdx.z * sA;
    float* Cb = C + (long)blockIdx.z * sC;
    const int tid = threadIdx.x;
    const int tx = tid & 15, ty = tid >> 4;

    float acc[8][8];
#pragma unroll
    for (int i = 0; i < 8; i++)
#pragma unroll
        for (int j = 0; j < 8; j++) acc[i][j] = 0.f;

    for (int k0 = 0; k0 < K; k0 += 8) {
#pragma unroll
        for (int i = 0; i < 4; i++) {
            int idx = tid + i * 256;
            if (ATRANS) {
                int kk = idx >> 7, mm = idx & 127;
                int m = bm + mm;
                As[kk][mm] = (m < M) ? Ab[(long)(k0 + kk) * lda + m] : 0.f;
            } else {
                int mm = idx >> 3, kk = idx & 7;
                int m = bm + mm;
                As[kk][mm] = (m < M) ? Ab[(long)m * lda + (k0 + kk)] : 0.f;
            }
            int kb = idx >> 7, nn = idx & 127;
            Bs[kb][nn] = Bm[(long)(k0 + kb) * N + bn + nn];
        }
        __syncthreads();
#pragma unroll
        for (int kk = 0; kk < 8; kk++) {
            float4 a0 = *(const float4*)&As[kk][ty * 8];
            float4 a1 = *(const float4*)&As[kk][ty * 8 + 4];
            float4 b0 = *(const float4*)&Bs[kk][tx * 8];
            float4 b1 = *(const float4*)&Bs[kk][tx * 8 + 4];
            float av[8] = {a0.x, a0.y, a0.z, a0.w, a1.x, a1.y, a1.z, a1.w};
            float bv_[8] = {b0.x, b0.y, b0.z, b0.w, b1.x, b1.y, b1.z, b1.w};
#pragma unroll
            for (int i = 0; i < 8; i++)
#pragma unroll
                for (int j = 0; j < 8; j++)
                    acc[i][j] = fmaf(av[i], bv_[j], acc[i][j]);
        }
        __syncthreads();
    }

    const float* Rb = RES ? (Rm + (long)blockIdx.z * sC) : (const float*)0;
#pragma unroll
    for (int i = 0; i < 8; i++) {
        int m = bm + ty * 8 + i;
        if (m >= M) continue;
#pragma unroll
        for (int j = 0; j < 8; j++) {
            int n = bn + tx * 8 + j;
            float val = acc[i][j] + bias[n];
            if (RES) val += Rb[(long)m * N + n];
            Cb[(long)m * N + n] = val;
        }
    }
}

// ---------------- offsets + attention weights ----------------
__global__ __launch_bounds__(128) void offattn_kernel(
    const float* __restrict__ Woff, const float* __restrict__ boff,
    const float* __restrict__ Wattn, const float* __restrict__ battn)
{
    __shared__ float qs[256];
    __shared__ float lg[32];
    const int row = blockIdx.x;
    const int tid = threadIdx.x;
    const float* qr = g_q + (long)row * DD;
    qs[tid] = qr[tid];
    qs[tid + 128] = qr[tid + 128];
    __syncthreads();

    if (tid < 64) {
        float s = boff[tid];
#pragma unroll 8
        for (int k = 0; k < 256; k++) s = fmaf(qs[k], Woff[k * 64 + tid], s);
        g_off[(long)row * 64 + tid] = s;
    } else if (tid < 96) {
        int j = tid - 64;
        float s = battn[j];
#pragma unroll 8
        for (int k = 0; k < 256; k++) s = fmaf(qs[k], Wattn[k * 32 + j], s);
        lg[j] = s;
    }
    __syncthreads();

    if (tid < 32) {
        float x = lg[tid];
        float m = x;
        m = fmaxf(m, __shfl_xor_sync(0xffffffffu, m, 1));
        m = fmaxf(m, __shfl_xor_sync(0xffffffffu, m, 2));
        float e = expf(x - m);
        float s = e;
        s += __shfl_xor_sync(0xffffffffu, s, 1);
        s += __shfl_xor_sync(0xffffffffu, s, 2);
        g_aw[(long)row * 32 + tid] = e / s;
    }
}

// ---------------- Bezier + bilinear sampling + weighted sum ----------------
__global__ __launch_bounds__(128) void sample_kernel(
    const float* __restrict__ ctrl, const float* __restrict__ pc)
{
    const int gw = blockIdx.x * 4 + (threadIdx.x >> 5);
    const int lane = threadIdx.x & 31;
    const int h = gw & 7;
    const int bn = gw >> 3;
    const int b = bn / NQ;

    const float* cp = ctrl + (long)bn * 8;
    const float cx0 = cp[0], cy0 = cp[1], cx1 = cp[2], cy1 = cp[3];
    const float cx2 = cp[4], cy2 = cp[5], cx3 = cp[6], cy3 = cp[7];

    const float p0 = pc[0], p1 = pc[1];
    const float invx = 1.f / (pc[3] - p0);
    const float invy = 1.f / (pc[4] - p1);

    const float* offr = g_off + (long)bn * 64 + h * 8;
    const float* awr = g_aw + (long)bn * 32 + h * 4;
    float awv[4], ox[4], oy[4];
#pragma unroll
    for (int p = 0; p < 4; p++) {
        awv[p] = awr[p];
        ox[p] = offr[p * 2];
        oy[p] = offr[p * 2 + 1];
    }

    const float* vb = g_v + (long)b * HWSZ * DD + h * HDIM + lane;
    float acc = 0.f;

#pragma unroll
    for (int k = 0; k < NK; k++) {
        float t = (float)k * (1.0f / (NK - 1));
        float u = 1.f - t;
        float b0 = u * u * u, b1 = 3.f * u * u * t, b2 = 3.f * u * t * t, b3 = t * t * t;
        float px = b0 * cx0 + b1 * cx1 + b2 * cx2 + b3 * cx3;
        float py = b0 * cy0 + b1 * cy1 + b2 * cy2 + b3 * cy3;
        float nx = fminf(fmaxf((px - p0) * invx, 0.01f), 0.99f);
        float ny = fminf(fmaxf((py - p1) * invy, 0.01f), 0.99f);

#pragma unroll
        for (int p = 0; p < 4; p++) {
            float gx = (nx + ox[p] * (1.f / WW)) * WW - 0.5f;
            float gy = (ny + oy[p] * (1.f / HH)) * HH - 0.5f;
            float fx = floorf(gx), fy = floorf(gy);
            float wx = gx - fx, wy = gy - fy;
            int xi = (int)fx, yi = (int)fy;
            float ap = awv[p];
#pragma unroll
            for (int c = 0; c < 4; c++) {
                int dx = c & 1, dy = c >> 1;
                int ix = xi + dx, iy = yi + dy;
                if (ix >= 0 && ix < WW && iy >= 0 && iy < HH) {
                    float wgt = ap * (dx ? wx : 1.f - wx) * (dy ? wy : 1.f - wy);
                    acc = fmaf(wgt, vb[(long)(iy * WW + ix) * DD], acc);
                }
            }
        }
    }
    g_s[(long)bn * DD + h * HDIM + lane] = acc;
}

// ---------------- launch ----------------
extern "C" void kernel_launch(void* const* d_in, const int* in_sizes, int n_in,
                              void* d_out, int out_size)
{
    const float* query = (const float*)d_in[0];
    const float* ctrl  = (const float*)d_in[1];
    const float* bev   = (const float*)d_in[2];
    const float* pc    = (const float*)d_in[4];
    const float* Wq    = (const float*)d_in[5];
    const float* bq    = (const float*)d_in[6];
    const float* Wv    = (const float*)d_in[7];
    const float* bv    = (const float*)d_in[8];
    const float* Woff  = (const float*)d_in[9];
    const float* boff  = (const float*)d_in[10];
    const float* Wattn = (const float*)d_in[11];
    const float* battn = (const float*)d_in[12];
    const float* Wmo   = (const float*)d_in[13];
    const float* bmo   = (const float*)d_in[14];
    const float* Wo    = (const float*)d_in[15];
    const float* bo    = (const float*)d_in[16];
    float* out = (float*)d_out;

    float *pq, *ps, *pt;
    cudaGetSymbolAddress((void**)&pq, g_q);
    cudaGetSymbolAddress((void**)&ps, g_s);
    cudaGetSymbolAddress((void**)&pt, g_t);

    cudaFuncSetAttribute(gemm_v, cudaFuncAttributeMaxDynamicSharedMemorySize, GEMM_SMEM);

    const int Mq = BB * NQ;   // 3600

    // q = query @ Wq + bq
    sgemm128<false, false><<<dim3(2, (Mq + 127) / 128, 1), 256>>>(
        query, Wq, bq, nullptr, pq, Mq, DD, DD, DD, 0, 0);

    // offsets + attention weights
    offattn_kernel<<<Mq, 128>>>(Woff, boff, Wattn, battn);

    // Wv -> WvT hi/lo (bf16 split)
    conv_wv<<<DD, 256>>>(Wv);

    // v = bev^T @ Wv + bv   via HMMA bf16 3-term split
    gemm_v<<<dim3(HWSZ / 64, BB), 256, GEMM_SMEM>>>(bev, bv);

    // bezier + bilinear sampling + attention-weighted sum
    sample_kernel<<<(BB * NQ * NHEADS) / 4, 128>>>(ctrl, pc);

    // t = s @ Wmo + bmo + q
    sgemm128<false, true><<<dim3(2, (Mq + 127) / 128, 1), 256>>>(
        ps, Wmo, bmo, pq, pt, Mq, DD, DD, DD, 0, 0);

    // out = t @ Wo + bo
    sgemm128<false, false><<<dim3(2, (Mq + 127) / 128, 1), 256>>>(
        pt, Wo, bo, nullptr, out, Mq, DD, DD, DD, 0, 0);
}

// round 4
// speedup vs baseline: 2.1822x; 1.3501x over previous
#include <cuda_runtime.h>
#include <cuda_bf16.h>
#include <cstdint>
#include <math.h>

// Problem constants (fixed shapes)
#define BB      4
#define NQ      900
#define DD      256
#define CH      256
#define HH      200
#define WW      200
#define HWSZ    40000
#define NHEADS  8
#define HDIM    32
#define NK      10
#define NPTS    4

// ---------------- scratch (device globals; no runtime allocation) ----------------
__device__ float g_q  [BB * NQ * DD];
__device__ float g_v  [BB * HWSZ * DD];          // projected BEV values (fp32)
__device__ float g_off[BB * NQ * NHEADS * NPTS * 2];
__device__ float g_aw [BB * NQ * NHEADS * NPTS];
__device__ float g_s  [BB * NQ * DD];
__device__ float g_t  [BB * NQ * DD];
__device__ __nv_bfloat16 g_bhi[DD * CH];         // WvT [n][k] hi
__device__ __nv_bfloat16 g_blo[DD * CH];         // WvT [n][k] lo

// ---------------- helpers ----------------
__device__ __forceinline__ uint32_t smem_u32(const void* p) {
    uint32_t a;
    asm("{ .reg .u64 t; cvta.to.shared.u64 t, %1; cvt.u32.u64 %0, t; }" : "=r"(a) : "l"(p));
    return a;
}
__device__ __forceinline__ uint32_t bf2u(__nv_bfloat16 a, __nv_bfloat16 b) {
    __nv_bfloat162 t(a, b);
    return *reinterpret_cast<uint32_t*>(&t);
}

#define LDSM_T(r, addr) \
    asm volatile("ldmatrix.sync.aligned.m8n8.x4.trans.shared.b16 {%0,%1,%2,%3}, [%4];" \
        : "=r"((r)[0]), "=r"((r)[1]), "=r"((r)[2]), "=r"((r)[3]) : "r"(addr))
#define LDSM(r, addr) \
    asm volatile("ldmatrix.sync.aligned.m8n8.x4.shared.b16 {%0,%1,%2,%3}, [%4];" \
        : "=r"((r)[0]), "=r"((r)[1]), "=r"((r)[2]), "=r"((r)[3]) : "r"(addr))
#define MMA_BF16(c, a, b0, b1) \
    asm volatile("mma.sync.aligned.m16n8k16.row.col.f32.bf16.bf16.f32 " \
        "{%0,%1,%2,%3},{%4,%5,%6,%7},{%8,%9},{%0,%1,%2,%3};" \
        : "+f"((c)[0]), "+f"((c)[1]), "+f"((c)[2]), "+f"((c)[3]) \
        : "r"((a)[0]), "r"((a)[1]), "r"((a)[2]), "r"((a)[3]), "r"(b0), "r"(b1))

__device__ __forceinline__ void split_store(char* dst_h, char* dst_l, uint32_t off, float4 v) {
    __nv_bfloat16 h0 = __float2bfloat16(v.x), h1 = __float2bfloat16(v.y);
    __nv_bfloat16 h2 = __float2bfloat16(v.z), h3 = __float2bfloat16(v.w);
    __nv_bfloat16 l0 = __float2bfloat16(v.x - __bfloat162float(h0));
    __nv_bfloat16 l1 = __float2bfloat16(v.y - __bfloat162float(h1));
    __nv_bfloat16 l2 = __float2bfloat16(v.z - __bfloat162float(h2));
    __nv_bfloat16 l3 = __float2bfloat16(v.w - __bfloat162float(h3));
    *(uint2*)(dst_h + off) = make_uint2(bf2u(h0, h1), bf2u(h2, h3));
    *(uint2*)(dst_l + off) = make_uint2(bf2u(l0, l1), bf2u(l2, l3));
}

// ---------------- Wv (K=256, N=256) -> WvT hi/lo [n][k] ----------------
__global__ __launch_bounds__(256) void conv_wv(const float* __restrict__ Wv)
{
    int idx = blockIdx.x * 256 + threadIdx.x;   // n*256 + k
    int n = idx >> 8, k = idx & 255;
    float v = Wv[k * DD + n];
    __nv_bfloat16 hi = __float2bfloat16(v);
    g_bhi[idx] = hi;
    g_blo[idx] = __float2bfloat16(v - __bfloat162float(hi));
}

// =====================================================================
// gemm_v: v[b,m,:] = bev^T[b,m,:] @ WvT^T + bv  (HMMA bf16 3-term split)
// CTA 64(m) x 128(n), K=256 in 4 chunks of 64. 8 warps = 2m x 4n (32x32 tiles).
// A smem [k 64][m 64+8]  trans-ldsm ; B smem [n 128][k 64+8] ldsm
// =====================================================================
#define V_APITCH 72
#define V_BPITCH 72
#define V_ASZ    (64 * V_APITCH * 2)            // 9216
#define V_BSZ    (128 * V_BPITCH * 2)           // 18432
#define V_AB(buf, hl) (((buf) * 2 + (hl)) * V_ASZ)               // 0..36864
#define V_BB(buf, hl) (36864 + ((buf) * 2 + (hl)) * V_BSZ)       // ..110592
#define V_SMEM 110592

__global__ void __launch_bounds__(256, 2) gemm_v(
    const float* __restrict__ bev, const float* __restrict__ bias)
{
    extern __shared__ char smem[];
    const uint32_t sb = smem_u32(smem);
    const int tid = threadIdx.x;
    const int lane = tid & 31;
    const int wid = tid >> 5;
    const int warp_m = wid & 1;
    const int warp_n = wid >> 1;
    const int n0 = blockIdx.x * 128;
    const int m0 = blockIdx.y * 64;
    const int b = blockIdx.z;

    const float* Ag = bev + (long)b * CH * HWSZ + m0;   // A[k][m]

    const int tile = lane >> 3;
    // A trans-ldsm: [k][m]
    const int kl = (lane & 7) + ((tile & 2) << 2);
    uint32_t aoff[2];
#pragma unroll
    for (int mf = 0; mf < 2; mf++) {
        int mcol = warp_m * 32 + mf * 16 + ((tile & 1) << 3);
        aoff[mf] = (uint32_t)(kl * V_APITCH + mcol) * 2;
    }
    // B ldsm: [n][k]
    uint32_t boff[2];
#pragma unroll
    for (int q = 0; q < 2; q++) {
        int row = warp_n * 32 + q * 16 + ((tile & 1) << 3) + (lane & 7);
        int kcol = (tile & 2) << 2;
        boff[q] = (uint32_t)(row * V_BPITCH + kcol) * 2;
    }

    float acc[2][4][4];
#pragma unroll
    for (int i = 0; i < 2; i++)
#pragma unroll
        for (int j = 0; j < 4; j++)
#pragma unroll
            for (int r = 0; r < 4; r++) acc[i][j][r] = 0.f;

    float4 rA[4];
    uint4 rBh[4], rBl[4];

    auto g_load = [&](int kc) {
        const int k0 = kc * 64;
#pragma unroll
        for (int p = 0; p < 4; p++) {
            int idx = tid + p * 256;
            int k = idx >> 4, m4 = (idx & 15) << 2;
            rA[p] = *(const float4*)(Ag + (long)(k0 + k) * HWSZ + m4);
        }
#pragma unroll
        for (int p = 0; p < 4; p++) {
            int idx = tid + p * 256;
            int n = idx >> 3, c = idx & 7;
            rBh[p] = *(const uint4*)(g_bhi + (n0 + n) * 256 + k0 + c * 8);
            rBl[p] = *(const uint4*)(g_blo + (n0 + n) * 256 + k0 + c * 8);
        }
    };
    auto s_store = [&](int buf) {
#pragma unroll
        for (int p = 0; p < 4; p++) {
            int idx = tid + p * 256;
            int k = idx >> 4, m4 = (idx & 15) << 2;
            split_store(smem + V_AB(buf, 0), smem + V_AB(buf, 1),
                        (uint32_t)(k * V_APITCH + m4) * 2, rA[p]);
        }
#pragma unroll
        for (int p = 0; p < 4; p++) {
            int idx = tid + p * 256;
            int n = idx >> 3, c = idx & 7;
            uint32_t off = (uint32_t)(n * V_BPITCH + c * 8) * 2;
            *(uint4*)(smem + V_BB(buf, 0) + off) = rBh[p];
            *(uint4*)(smem + V_BB(buf, 1) + off) = rBl[p];
        }
    };

    g_load(0);
    s_store(0);
    __syncthreads();

    for (int kc = 0; kc < 4; kc++) {
        const int cur = kc & 1;
        if (kc < 3) g_load(kc + 1);

        const uint32_t Ah = sb + V_AB(cur, 0), Al = sb + V_AB(cur, 1);
        const uint32_t Bh = sb + V_BB(cur, 0), Bl = sb + V_BB(cur, 1);
#pragma unroll
        for (int ks = 0; ks < 4; ks++) {
            uint32_t ah[2][4], al[2][4], bh[2][4], bl[2][4];
#pragma unroll
            for (int mf = 0; mf < 2; mf++) {
                LDSM_T(ah[mf], Ah + aoff[mf] + ks * (16 * V_APITCH * 2));
                LDSM_T(al[mf], Al + aoff[mf] + ks * (16 * V_APITCH * 2));
            }
#pragma unroll
            for (int q = 0; q < 2; q++) {
                LDSM(bh[q], Bh + boff[q] + ks * 32);
                LDSM(bl[q], Bl + boff[q] + ks * 32);
            }
#pragma unroll
            for (int mf = 0; mf < 2; mf++)
#pragma unroll
                for (int nf = 0; nf < 4; nf++) {
                    int q = nf >> 1, h = nf & 1;
                    MMA_BF16(acc[mf][nf], ah[mf], bh[q][h], bh[q][h + 2]);
                    MMA_BF16(acc[mf][nf], ah[mf], bl[q][h], bl[q][h + 2]);
                    MMA_BF16(acc[mf][nf], al[mf], bh[q][h], bh[q][h + 2]);
                }
        }
        if (kc < 3) s_store(1 - cur);
        __syncthreads();
    }

    float* vout = g_v + ((long)b * HWSZ + m0) * DD + n0;
#pragma unroll
    for (int mf = 0; mf < 2; mf++) {
        int mrow = warp_m * 32 + mf * 16 + (lane >> 2);
#pragma unroll
        for (int nf = 0; nf < 4; nf++) {
            int n = warp_n * 32 + nf * 8 + (lane & 3) * 2;
            float2 bb = *(const float2*)(bias + n0 + n);
            *(float2*)(vout + (long)mrow * DD + n) =
                make_float2(acc[mf][nf][0] + bb.x, acc[mf][nf][1] + bb.y);
            *(float2*)(vout + (long)(mrow + 8) * DD + n) =
                make_float2(acc[mf][nf][2] + bb.x, acc[mf][nf][3] + bb.y);
        }
    }
}

// =====================================================================
// gemm_small: C[M x 256] = A[M x 256] @ W[256 x 256] + bias (+R)
// A row-major fp32 (split on the fly), W row-major [k][n] fp32 (split on fly).
// CTA 64(m) x 128(n), K chunks of 64, 8 warps = 2m x 4n.
// A smem [m 64][k 64+8] ldsm ; B smem [k 64][n 128+8] trans-ldsm
// =====================================================================
#define S_APITCH 72
#define S_BPITCH 136
#define S_ASZ    (64 * S_APITCH * 2)            // 9216
#define S_BSZ    (64 * S_BPITCH * 2)            // 17408
#define S_AB(buf, hl) (((buf) * 2 + (hl)) * S_ASZ)               // 0..36864
#define S_BB(buf, hl) (36864 + ((buf) * 2 + (hl)) * S_BSZ)       // ..106496
#define S_SMEM 106496

template <bool RES>
__global__ void __launch_bounds__(256) gemm_small(
    const float* __restrict__ A, const float* __restrict__ Wm,
    const float* __restrict__ bias, const float* __restrict__ Rm,
    float* __restrict__ C, int M)
{
    extern __shared__ char smem[];
    const uint32_t sb = smem_u32(smem);
    const int tid = threadIdx.x;
    const int lane = tid & 31;
    const int wid = tid >> 5;
    const int warp_m = wid & 1;
    const int warp_n = wid >> 1;
    const int n0 = blockIdx.x * 128;
    const int m0 = blockIdx.y * 64;

    const int tile = lane >> 3;
    // A ldsm (non-trans): [m][k]
    uint32_t aoff[2];
#pragma unroll
    for (int mf = 0; mf < 2; mf++) {
        int ml = warp_m * 32 + mf * 16 + ((tile & 1) << 3) + (lane & 7);
        int kcol = (tile & 2) << 2;
        aoff[mf] = (uint32_t)(ml * S_APITCH + kcol) * 2;
    }
    // B trans-ldsm: [k][n]
    uint32_t boff[2];
#pragma unroll
    for (int q = 0; q < 2; q++) {
        int kr = (lane & 7) + ((tile & 2) << 2);
        int nc = warp_n * 32 + q * 16 + ((tile & 1) << 3);
        boff[q] = (uint32_t)(kr * S_BPITCH + nc) * 2;
    }

    float acc[2][4][4];
#pragma unroll
    for (int i = 0; i < 2; i++)
#pragma unroll
        for (int j = 0; j < 4; j++)
#pragma unroll
            for (int r = 0; r < 4; r++) acc[i][j][r] = 0.f;

    float4 rA[4], rB[8];

    auto g_load = [&](int kc) {
        const int k0 = kc * 64;
#pragma unroll
        for (int p = 0; p < 4; p++) {
            int idx = tid + p * 256;
            int m = idx >> 4, k4 = (idx & 15) << 2;
            rA[p] = (m0 + m < M) ? *(const float4*)(A + (long)(m0 + m) * DD + k0 + k4)
                                 : make_float4(0.f, 0.f, 0.f, 0.f);
        }
#pragma unroll
        for (int p = 0; p < 8; p++) {
            int idx = tid + p * 256;
            int k = idx >> 5, n4 = (idx & 31) << 2;
            rB[p] = *(const float4*)(Wm + (long)(k0 + k) * DD + n0 + n4);
        }
    };
    auto s_store = [&](int buf) {
#pragma unroll
        for (int p = 0; p < 4; p++) {
            int idx = tid + p * 256;
            int m = idx >> 4, k4 = (idx & 15) << 2;
            split_store(smem + S_AB(buf, 0), smem + S_AB(buf, 1),
                        (uint32_t)(m * S_APITCH + k4) * 2, rA[p]);
        }
#pragma unroll
        for (int p = 0; p < 8; p++) {
            int idx = tid + p * 256;
            int k = idx >> 5, n4 = (idx & 31) << 2;
            split_store(smem + S_BB(buf, 0), smem + S_BB(buf, 1),
                        (uint32_t)(k * S_BPITCH + n4) * 2, rB[p]);
        }
    };

    g_load(0);
    s_store(0);
    __syncthreads();

    for (int kc = 0; kc < 4; kc++) {
        const int cur = kc & 1;
        if (kc < 3) g_load(kc + 1);

        const uint32_t Ah = sb + S_AB(cur, 0), Al = sb + S_AB(cur, 1);
        const uint32_t Bh = sb + S_BB(cur, 0), Bl = sb + S_BB(cur, 1);
#pragma unroll
        for (int ks = 0; ks < 4; ks++) {
            uint32_t ah[2][4], al[2][4], bh[2][4], bl[2][4];
#pragma unroll
            for (int mf = 0; mf < 2; mf++) {
                LDSM(ah[mf], Ah + aoff[mf] + ks * 32);
                LDSM(al[mf], Al + aoff[mf] + ks * 32);
            }
#pragma unroll
            for (int q = 0; q < 2; q++) {
                LDSM_T(bh[q], Bh + boff[q] + ks * (16 * S_BPITCH * 2));
                LDSM_T(bl[q], Bl + boff[q] + ks * (16 * S_BPITCH * 2));
            }
#pragma unroll
            for (int mf = 0; mf < 2; mf++)
#pragma unroll
                for (int nf = 0; nf < 4; nf++) {
                    int q = nf >> 1, h = nf & 1;
                    MMA_BF16(acc[mf][nf], ah[mf], bh[q][h], bh[q][h + 2]);
                    MMA_BF16(acc[mf][nf], ah[mf], bl[q][h], bl[q][h + 2]);
                    MMA_BF16(acc[mf][nf], al[mf], bh[q][h], bh[q][h + 2]);
                }
        }
        if (kc < 3) s_store(1 - cur);
        __syncthreads();
    }

#pragma unroll
    for (int mf = 0; mf < 2; mf++) {
        int mrow = warp_m * 32 + mf * 16 + (lane >> 2);
#pragma unroll
        for (int nf = 0; nf < 4; nf++) {
            int n = warp_n * 32 + nf * 8 + (lane & 3) * 2;
            float2 bb = *(const float2*)(bias + n0 + n);
            float2 s0 = make_float2(acc[mf][nf][0] + bb.x, acc[mf][nf][1] + bb.y);
            float2 s1 = make_float2(acc[mf][nf][2] + bb.x, acc[mf][nf][3] + bb.y);
            if (RES) {
                if (m0 + mrow < M) {
                    float2 r = *(const float2*)(Rm + (long)(m0 + mrow) * DD + n0 + n);
                    s0.x += r.x; s0.y += r.y;
                }
                if (m0 + mrow + 8 < M) {
                    float2 r = *(const float2*)(Rm + (long)(m0 + mrow + 8) * DD + n0 + n);
                    s1.x += r.x; s1.y += r.y;
                }
            }
            if (m0 + mrow < M)
                *(float2*)(C + (long)(m0 + mrow) * DD + n0 + n) = s0;
            if (m0 + mrow + 8 < M)
                *(float2*)(C + (long)(m0 + mrow + 8) * DD + n0 + n) = s1;
        }
    }
}

// ---------------- offsets + attention weights ----------------
__global__ __launch_bounds__(128) void offattn_kernel(
    const float* __restrict__ Woff, const float* __restrict__ boff,
    const float* __restrict__ Wattn, const float* __restrict__ battn)
{
    __shared__ float qs[256];
    __shared__ float lg[32];
    const int row = blockIdx.x;
    const int tid = threadIdx.x;
    const float* qr = g_q + (long)row * DD;
    qs[tid] = qr[tid];
    qs[tid + 128] = qr[tid + 128];
    __syncthreads();

    if (tid < 64) {
        float s = boff[tid];
#pragma unroll 8
        for (int k = 0; k < 256; k++) s = fmaf(qs[k], Woff[k * 64 + tid], s);
        g_off[(long)row * 64 + tid] = s;
    } else if (tid < 96) {
        int j = tid - 64;
        float s = battn[j];
#pragma unroll 8
        for (int k = 0; k < 256; k++) s = fmaf(qs[k], Wattn[k * 32 + j], s);
        lg[j] = s;
    }
    __syncthreads();

    if (tid < 32) {
        float x = lg[tid];
        float m = x;
        m = fmaxf(m, __shfl_xor_sync(0xffffffffu, m, 1));
        m = fmaxf(m, __shfl_xor_sync(0xffffffffu, m, 2));
        float e = expf(x - m);
        float s = e;
        s += __shfl_xor_sync(0xffffffffu, s, 1);
        s += __shfl_xor_sync(0xffffffffu, s, 2);
        g_aw[(long)row * 32 + tid] = e / s;
    }
}

// ---------------- Bezier + bilinear sampling + weighted sum ----------------
__global__ __launch_bounds__(128) void sample_kernel(
    const float* __restrict__ ctrl, const float* __restrict__ pc)
{
    const int gw = blockIdx.x * 4 + (threadIdx.x >> 5);
    const int lane = threadIdx.x & 31;
    const int h = gw & 7;
    const int bn = gw >> 3;
    const int b = bn / NQ;

    const float* cp = ctrl + (long)bn * 8;
    const float cx0 = cp[0], cy0 = cp[1], cx1 = cp[2], cy1 = cp[3];
    const float cx2 = cp[4], cy2 = cp[5], cx3 = cp[6], cy3 = cp[7];

    const float p0 = pc[0], p1 = pc[1];
    const float invx = 1.f / (pc[3] - p0);
    const float invy = 1.f / (pc[4] - p1);

    const float* offr = g_off + (long)bn * 64 + h * 8;
    const float* awr = g_aw + (long)bn * 32 + h * 4;
    float awv[4], ox[4], oy[4];
#pragma unroll
    for (int p = 0; p < 4; p++) {
        awv[p] = awr[p];
        ox[p] = offr[p * 2];
        oy[p] = offr[p * 2 + 1];
    }

    const float* vb = g_v + (long)b * HWSZ * DD + h * HDIM + lane;
    float acc = 0.f;

#pragma unroll
    for (int k = 0; k < NK; k++) {
        float t = (float)k * (1.0f / (NK - 1));
        float u = 1.f - t;
        float b0 = u * u * u, b1 = 3.f * u * u * t, b2 = 3.f * u * t * t, b3 = t * t * t;
        float px = b0 * cx0 + b1 * cx1 + b2 * cx2 + b3 * cx3;
        float py = b0 * cy0 + b1 * cy1 + b2 * cy2 + b3 * cy3;
        float nx = fminf(fmaxf((px - p0) * invx, 0.01f), 0.99f);
        float ny = fminf(fmaxf((py - p1) * invy, 0.01f), 0.99f);

#pragma unroll
        for (int p = 0; p < 4; p++) {
            float gx = (nx + ox[p] * (1.f / WW)) * WW - 0.5f;
            float gy = (ny + oy[p] * (1.f / HH)) * HH - 0.5f;
            float fx = floorf(gx), fy = floorf(gy);
            float wx = gx - fx, wy = gy - fy;
            int xi = (int)fx, yi = (int)fy;
            float ap = awv[p];
#pragma unroll
            for (int c = 0; c < 4; c++) {
                int dx = c & 1, dy = c >> 1;
                int ix = xi + dx, iy = yi + dy;
                if (ix >= 0 && ix < WW && iy >= 0 && iy < HH) {
                    float wgt = ap * (dx ? wx : 1.f - wx) * (dy ? wy : 1.f - wy);
                    acc = fmaf(wgt, vb[(long)(iy * WW + ix) * DD], acc);
                }
            }
        }
    }
    g_s[(long)bn * DD + h * HDIM + lane] = acc;
}

// ---------------- launch ----------------
extern "C" void kernel_launch(void* const* d_in, const int* in_sizes, int n_in,
                              void* d_out, int out_size)
{
    const float* query = (const float*)d_in[0];
    const float* ctrl  = (const float*)d_in[1];
    const float* bev   = (const float*)d_in[2];
    const float* pc    = (const float*)d_in[4];
    const float* Wq    = (const float*)d_in[5];
    const float* bq    = (const float*)d_in[6];
    const float* Wv    = (const float*)d_in[7];
    const float* bv    = (const float*)d_in[8];
    const float* Woff  = (const float*)d_in[9];
    const float* boff  = (const float*)d_in[10];
    const float* Wattn = (const float*)d_in[11];
    const float* battn = (const float*)d_in[12];
    const float* Wmo   = (const float*)d_in[13];
    const float* bmo   = (const float*)d_in[14];
    const float* Wo    = (const float*)d_in[15];
    const float* bo    = (const float*)d_in[16];
    float* out = (float*)d_out;

    float *pq, *ps, *pt;
    cudaGetSymbolAddress((void**)&pq, g_q);
    cudaGetSymbolAddress((void**)&ps, g_s);
    cudaGetSymbolAddress((void**)&pt, g_t);

    cudaFuncSetAttribute(gemm_v, cudaFuncAttributeMaxDynamicSharedMemorySize, V_SMEM);
    cudaFuncSetAttribute(gemm_small<false>, cudaFuncAttributeMaxDynamicSharedMemorySize, S_SMEM);
    cudaFuncSetAttribute(gemm_small<true>, cudaFuncAttributeMaxDynamicSharedMemorySize, S_SMEM);

    const int Mq = BB * NQ;                     // 3600
    const dim3 sg_grid(2, (Mq + 63) / 64);      // 2 x 57

    // q = query @ Wq + bq
    gemm_small<false><<<sg_grid, 256, S_SMEM>>>(query, Wq, bq, nullptr, pq, Mq);

    // offsets + attention weights
    offattn_kernel<<<Mq, 128>>>(Woff, boff, Wattn, battn);

    // Wv -> WvT hi/lo (bf16 split)
    conv_wv<<<DD, 256>>>(Wv);

    // v = bev^T @ Wv + bv
    gemm_v<<<dim3(2, HWSZ / 64, BB), 256, V_SMEM>>>(bev, bv);

    // bezier + bilinear sampling + attention-weighted sum
    sample_kernel<<<(BB * NQ * NHEADS) / 4, 128>>>(ctrl, pc);

    // t = s @ Wmo + bmo + q
    gemm_small<true><<<sg_grid, 256, S_SMEM>>>(ps, Wmo, bmo, pq, pt, Mq);

    // out = t @ Wo + bo
    gemm_small<false><<<sg_grid, 256, S_SMEM>>>(pt, Wo, bo, nullptr, out, Mq);
}

// round 5
// speedup vs baseline: 2.7648x; 1.2670x over previous
#include <cuda_runtime.h>
#include <cuda_bf16.h>
#include <cstdint>
#include <math.h>

// Problem constants (fixed shapes)
#define BB      4
#define NQ      900
#define DD      256
#define CH      256
#define HH      200
#define WW      200
#define HWSZ    40000
#define NHEADS  8
#define HDIM    32
#define NK      10
#define NPTS    4

// ---------------- scratch (device globals; no runtime allocation) ----------------
__device__ float g_q  [BB * NQ * DD];
__device__ float g_v  [BB * HWSZ * DD];          // projected BEV values (fp32)
__device__ float g_off[BB * NQ * NHEADS * NPTS * 2];
__device__ float g_aw [BB * NQ * NHEADS * NPTS];
__device__ float g_s  [BB * NQ * DD];
__device__ float g_t  [BB * NQ * DD];
__device__ __nv_bfloat16 g_bhi[DD * CH];         // WvT [n][k] hi
__device__ __nv_bfloat16 g_blo[DD * CH];         // WvT [n][k] lo

// ---------------- helpers ----------------
__device__ __forceinline__ uint32_t smem_u32(const void* p) {
    uint32_t a;
    asm("{ .reg .u64 t; cvta.to.shared.u64 t, %1; cvt.u32.u64 %0, t; }" : "=r"(a) : "l"(p));
    return a;
}
__device__ __forceinline__ uint32_t bf2u(__nv_bfloat16 a, __nv_bfloat16 b) {
    __nv_bfloat162 t(a, b);
    return *reinterpret_cast<uint32_t*>(&t);
}

#define LDSM_T(r, addr) \
    asm volatile("ldmatrix.sync.aligned.m8n8.x4.trans.shared.b16 {%0,%1,%2,%3}, [%4];" \
        : "=r"((r)[0]), "=r"((r)[1]), "=r"((r)[2]), "=r"((r)[3]) : "r"(addr))
#define LDSM(r, addr) \
    asm volatile("ldmatrix.sync.aligned.m8n8.x4.shared.b16 {%0,%1,%2,%3}, [%4];" \
        : "=r"((r)[0]), "=r"((r)[1]), "=r"((r)[2]), "=r"((r)[3]) : "r"(addr))
#define MMA_BF16(c, a, b0, b1) \
    asm volatile("mma.sync.aligned.m16n8k16.row.col.f32.bf16.bf16.f32 " \
        "{%0,%1,%2,%3},{%4,%5,%6,%7},{%8,%9},{%0,%1,%2,%3};" \
        : "+f"((c)[0]), "+f"((c)[1]), "+f"((c)[2]), "+f"((c)[3]) \
        : "r"((a)[0]), "r"((a)[1]), "r"((a)[2]), "r"((a)[3]), "r"(b0), "r"(b1))
#define CP16(dst, src) \
    asm volatile("cp.async.cg.shared.global [%0], [%1], 16;" :: "r"(dst), "l"(src))
#define CP_COMMIT()  asm volatile("cp.async.commit_group;" ::: "memory")
#define CP_WAIT0()   asm volatile("cp.async.wait_group 0;" ::: "memory")

__device__ __forceinline__ void split_store(char* dst_h, char* dst_l, uint32_t off, float4 v) {
    __nv_bfloat16 h0 = __float2bfloat16(v.x), h1 = __float2bfloat16(v.y);
    __nv_bfloat16 h2 = __float2bfloat16(v.z), h3 = __float2bfloat16(v.w);
    __nv_bfloat16 l0 = __float2bfloat16(v.x - __bfloat162float(h0));
    __nv_bfloat16 l1 = __float2bfloat16(v.y - __bfloat162float(h1));
    __nv_bfloat16 l2 = __float2bfloat16(v.z - __bfloat162float(h2));
    __nv_bfloat16 l3 = __float2bfloat16(v.w - __bfloat162float(h3));
    *(uint2*)(dst_h + off) = make_uint2(bf2u(h0, h1), bf2u(h2, h3));
    *(uint2*)(dst_l + off) = make_uint2(bf2u(l0, l1), bf2u(l2, l3));
}

// ---------------- Wv (K=256, N=256) -> WvT hi/lo [n][k] ----------------
__global__ __launch_bounds__(256) void conv_wv(const float* __restrict__ Wv)
{
    int idx = blockIdx.x * 256 + threadIdx.x;   // n*256 + k
    int n = idx >> 8, k = idx & 255;
    float v = Wv[k * DD + n];
    __nv_bfloat16 hi = __float2bfloat16(v);
    g_bhi[idx] = hi;
    g_blo[idx] = __float2bfloat16(v - __bfloat162float(hi));
}

// =====================================================================
// gemm_v: v[b,m,:] = bev^T[b,m,:] @ WvT^T + bv  (HMMA bf16 3-term split)
// CTA 64(m) x 256(n) FULL N, K=256 in 8 chunks of 32.
// 8 warps = 2m x 4n (warp tile 32 x 64).
// A: fp32 LDG -> in-reg split -> STS [k 32][m 64 pitch72els], trans-ldsm
// B: cp.async bf16 gmem -> smem [n 256][k 32 pitch40els], ldsm
// =====================================================================
#define V_APITCH_B 144                           // bytes per A k-row (72 els)
#define V_BPITCH_B 80                            // bytes per B n-row (40 els)
#define V_ASZ      (32 * V_APITCH_B)             // 4608
#define V_BSZ      (256 * V_BPITCH_B)            // 20480
#define V_AB(buf, hl) (((buf) * 2 + (hl)) * V_ASZ)                 // 0..18432
#define V_BB(buf, hl) (18432 + ((buf) * 2 + (hl)) * V_BSZ)         // ..100352
#define V_SMEM 100352

__global__ void __launch_bounds__(256, 2) gemm_v(
    const float* __restrict__ bev, const float* __restrict__ bias)
{
    extern __shared__ char smem[];
    const uint32_t sb = smem_u32(smem);
    const int tid = threadIdx.x;
    const int lane = tid & 31;
    const int wid = tid >> 5;
    const int warp_m = wid & 1;                  // 2 warps over m (32 each)
    const int warp_n = wid >> 1;                 // 4 warps over n (64 each)
    const int m0 = blockIdx.x * 64;
    const int b = blockIdx.y;

    const float* Ag = bev + (long)b * CH * HWSZ + m0;   // A[k][m]
    const __nv_bfloat16* Bh_g = g_bhi;
    const __nv_bfloat16* Bl_g = g_blo;

    const int tile = lane >> 3;
    // A trans-ldsm offsets: [k][m]
    const int kl = (lane & 7) + ((tile & 2) << 2);
    uint32_t aoff[2];
#pragma unroll
    for (int mf = 0; mf < 2; mf++) {
        int mcol = warp_m * 32 + mf * 16 + ((tile & 1) << 3);
        aoff[mf] = (uint32_t)(kl * V_APITCH_B + mcol * 2);
    }
    // B ldsm offsets: [n][k]
    uint32_t boff[4];
#pragma unroll
    for (int q = 0; q < 4; q++) {
        int row = warp_n * 64 + q * 16 + ((tile & 1) << 3) + (lane & 7);
        int kcol = (tile & 2) << 2;
        boff[q] = (uint32_t)(row * V_BPITCH_B + kcol * 2);
    }

    float acc[2][8][4];
#pragma unroll
    for (int i = 0; i < 2; i++)
#pragma unroll
        for (int j = 0; j < 8; j++)
#pragma unroll
            for (int r = 0; r < 4; r++) acc[i][j][r] = 0.f;

    float4 rA[2];

    auto a_ldg = [&](int kc) {
        const int k0 = kc * 32;
#pragma unroll
        for (int p = 0; p < 2; p++) {
            int f = tid + p * 256;               // float4 id 0..511
            int k = f >> 4, m4 = (f & 15) << 2;
            rA[p] = *(const float4*)(Ag + (long)(k0 + k) * HWSZ + m4);
        }
    };
    auto a_sts = [&](int buf) {
#pragma unroll
        for (int p = 0; p < 2; p++) {
            int f = tid + p * 256;
            int k = f >> 4, m4 = (f & 15) << 2;
            split_store(smem + V_AB(buf, 0), smem + V_AB(buf, 1),
                        (uint32_t)(k * V_APITCH_B + m4 * 2), rA[p]);
        }
    };
    auto b_cp = [&](int kc, int buf) {
        const int k0 = kc * 32;
#pragma unroll
        for (int p = 0; p < 4; p++) {
            int e = tid + p * 256;               // 0..1023
            int n = e >> 2, c4 = e & 3;
            uint32_t d0 = sb + V_BB(buf, 0) + n * V_BPITCH_B + c4 * 16;
            CP16(d0, (const void*)(Bh_g + n * 256 + k0 + c4 * 8));
            uint32_t d1 = sb + V_BB(buf, 1) + n * V_BPITCH_B + c4 * 16;
            CP16(d1, (const void*)(Bl_g + n * 256 + k0 + c4 * 8));
        }
    };

    // prologue
    b_cp(0, 0);
    CP_COMMIT();
    a_ldg(0);
    a_sts(0);
    CP_WAIT0();
    __syncthreads();

    for (int kc = 0; kc < 8; kc++) {
        const int cur = kc & 1;
        if (kc < 7) {
            b_cp(kc + 1, 1 - cur);
            CP_COMMIT();
            a_ldg(kc + 1);
        }

        const uint32_t Ah = sb + V_AB(cur, 0), Al = sb + V_AB(cur, 1);
        const uint32_t Bh = sb + V_BB(cur, 0), Bl = sb + V_BB(cur, 1);
#pragma unroll
        for (int ks = 0; ks < 2; ks++) {
            uint32_t ah[2][4], al[2][4];
#pragma unroll
            for (int mf = 0; mf < 2; mf++) {
                LDSM_T(ah[mf], Ah + aoff[mf] + ks * (16 * V_APITCH_B));
                LDSM_T(al[mf], Al + aoff[mf] + ks * (16 * V_APITCH_B));
            }
#pragma unroll
            for (int q = 0; q < 4; q++) {
                uint32_t bh[4], bl[4];
                LDSM(bh, Bh + boff[q] + ks * 32);
                LDSM(bl, Bl + boff[q] + ks * 32);
#pragma unroll
                for (int h = 0; h < 2; h++) {
                    const int nf = q * 2 + h;
#pragma unroll
                    for (int mf = 0; mf < 2; mf++) {
                        MMA_BF16(acc[mf][nf], ah[mf], bh[h], bh[h + 2]);
                        MMA_BF16(acc[mf][nf], ah[mf], bl[h], bl[h + 2]);
                        MMA_BF16(acc[mf][nf], al[mf], bh[h], bh[h + 2]);
                    }
                }
            }
        }

        if (kc < 7) {
            a_sts(1 - cur);
            CP_WAIT0();
        }
        __syncthreads();
    }

    // epilogue: direct float2 stores
    float* vout = g_v + ((long)b * HWSZ + m0) * DD;
#pragma unroll
    for (int mf = 0; mf < 2; mf++) {
        int mrow = warp_m * 32 + mf * 16 + (lane >> 2);
#pragma unroll
        for (int nf = 0; nf < 8; nf++) {
            int n = warp_n * 64 + nf * 8 + (lane & 3) * 2;
            float2 bb = *(const float2*)(bias + n);
            *(float2*)(vout + (long)mrow * DD + n) =
                make_float2(acc[mf][nf][0] + bb.x, acc[mf][nf][1] + bb.y);
            *(float2*)(vout + (long)(mrow + 8) * DD + n) =
                make_float2(acc[mf][nf][2] + bb.x, acc[mf][nf][3] + bb.y);
        }
    }
}

// =====================================================================
// gemm_small: C[M x 256] = A[M x 256] @ W[256 x 256] + bias (+R)
// =====================================================================
#define S_APITCH 72
#define S_BPITCH 136
#define S_ASZ    (64 * S_APITCH * 2)            // 9216
#define S_BSZ    (64 * S_BPITCH * 2)            // 17408
#define S_AB(buf, hl) (((buf) * 2 + (hl)) * S_ASZ)               // 0..36864
#define S_BB(buf, hl) (36864 + ((buf) * 2 + (hl)) * S_BSZ)       // ..106496
#define S_SMEM 106496

template <bool RES>
__global__ void __launch_bounds__(256) gemm_small(
    const float* __restrict__ A, const float* __restrict__ Wm,
    const float* __restrict__ bias, const float* __restrict__ Rm,
    float* __restrict__ C, int M)
{
    extern __shared__ char smem[];
    const uint32_t sb = smem_u32(smem);
    const int tid = threadIdx.x;
    const int lane = tid & 31;
    const int wid = tid >> 5;
    const int warp_m = wid & 1;
    const int warp_n = wid >> 1;
    const int n0 = blockIdx.x * 128;
    const int m0 = blockIdx.y * 64;

    const int tile = lane >> 3;
    uint32_t aoff[2];
#pragma unroll
    for (int mf = 0; mf < 2; mf++) {
        int ml = warp_m * 32 + mf * 16 + ((tile & 1) << 3) + (lane & 7);
        int kcol = (tile & 2) << 2;
        aoff[mf] = (uint32_t)(ml * S_APITCH + kcol) * 2;
    }
    uint32_t boff[2];
#pragma unroll
    for (int q = 0; q < 2; q++) {
        int kr = (lane & 7) + ((tile & 2) << 2);
        int nc = warp_n * 32 + q * 16 + ((tile & 1) << 3);
        boff[q] = (uint32_t)(kr * S_BPITCH + nc) * 2;
    }

    float acc[2][4][4];
#pragma unroll
    for (int i = 0; i < 2; i++)
#pragma unroll
        for (int j = 0; j < 4; j++)
#pragma unroll
            for (int r = 0; r < 4; r++) acc[i][j][r] = 0.f;

    float4 rA[4], rB[8];

    auto g_load = [&](int kc) {
        const int k0 = kc * 64;
#pragma unroll
        for (int p = 0; p < 4; p++) {
            int idx = tid + p * 256;
            int m = idx >> 4, k4 = (idx & 15) << 2;
            rA[p] = (m0 + m < M) ? *(const float4*)(A + (long)(m0 + m) * DD + k0 + k4)
                                 : make_float4(0.f, 0.f, 0.f, 0.f);
        }
#pragma unroll
        for (int p = 0; p < 8; p++) {
            int idx = tid + p * 256;
            int k = idx >> 5, n4 = (idx & 31) << 2;
            rB[p] = *(const float4*)(Wm + (long)(k0 + k) * DD + n0 + n4);
        }
    };
    auto s_store = [&](int buf) {
#pragma unroll
        for (int p = 0; p < 4; p++) {
            int idx = tid + p * 256;
            int m = idx >> 4, k4 = (idx & 15) << 2;
            split_store(smem + S_AB(buf, 0), smem + S_AB(buf, 1),
                        (uint32_t)(m * S_APITCH + k4) * 2, rA[p]);
        }
#pragma unroll
        for (int p = 0; p < 8; p++) {
            int idx = tid + p * 256;
            int k = idx >> 5, n4 = (idx & 31) << 2;
            split_store(smem + S_BB(buf, 0), smem + S_BB(buf, 1),
                        (uint32_t)(k * S_BPITCH + n4) * 2, rB[p]);
        }
    };

    g_load(0);
    s_store(0);
    __syncthreads();

    for (int kc = 0; kc < 4; kc++) {
        const int cur = kc & 1;
        if (kc < 3) g_load(kc + 1);

        const uint32_t Ah = sb + S_AB(cur, 0), Al = sb + S_AB(cur, 1);
        const uint32_t Bh = sb + S_BB(cur, 0), Bl = sb + S_BB(cur, 1);
#pragma unroll
        for (int ks = 0; ks < 4; ks++) {
            uint32_t ah[2][4], al[2][4], bh[2][4], bl[2][4];
#pragma unroll
            for (int mf = 0; mf < 2; mf++) {
                LDSM(ah[mf], Ah + aoff[mf] + ks * 32);
                LDSM(al[mf], Al + aoff[mf] + ks * 32);
            }
#pragma unroll
            for (int q = 0; q < 2; q++) {
                LDSM_T(bh[q], Bh + boff[q] + ks * (16 * S_BPITCH * 2));
                LDSM_T(bl[q], Bl + boff[q] + ks * (16 * S_BPITCH * 2));
            }
#pragma unroll
            for (int mf = 0; mf < 2; mf++)
#pragma unroll
                for (int nf = 0; nf < 4; nf++) {
                    int q = nf >> 1, h = nf & 1;
                    MMA_BF16(acc[mf][nf], ah[mf], bh[q][h], bh[q][h + 2]);
                    MMA_BF16(acc[mf][nf], ah[mf], bl[q][h], bl[q][h + 2]);
                    MMA_BF16(acc[mf][nf], al[mf], bh[q][h], bh[q][h + 2]);
                }
        }
        if (kc < 3) s_store(1 - cur);
        __syncthreads();
    }

#pragma unroll
    for (int mf = 0; mf < 2; mf++) {
        int mrow = warp_m * 32 + mf * 16 + (lane >> 2);
#pragma unroll
        for (int nf = 0; nf < 4; nf++) {
            int n = warp_n * 32 + nf * 8 + (lane & 3) * 2;
            float2 bb = *(const float2*)(bias + n0 + n);
            float2 s0 = make_float2(acc[mf][nf][0] + bb.x, acc[mf][nf][1] + bb.y);
            float2 s1 = make_float2(acc[mf][nf][2] + bb.x, acc[mf][nf][3] + bb.y);
            if (RES) {
                if (m0 + mrow < M) {
                    float2 r = *(const float2*)(Rm + (long)(m0 + mrow) * DD + n0 + n);
                    s0.x += r.x; s0.y += r.y;
                }
                if (m0 + mrow + 8 < M) {
                    float2 r = *(const float2*)(Rm + (long)(m0 + mrow + 8) * DD + n0 + n);
                    s1.x += r.x; s1.y += r.y;
                }
            }
            if (m0 + mrow < M)
                *(float2*)(C + (long)(m0 + mrow) * DD + n0 + n) = s0;
            if (m0 + mrow + 8 < M)
                *(float2*)(C + (long)(m0 + mrow + 8) * DD + n0 + n) = s1;
        }
    }
}

// ---------------- offsets + attention weights ----------------
__global__ __launch_bounds__(128) void offattn_kernel(
    const float* __restrict__ Woff, const float* __restrict__ boff,
    const float* __restrict__ Wattn, const float* __restrict__ battn)
{
    __shared__ float qs[256];
    __shared__ float lg[32];
    const int row = blockIdx.x;
    const int tid = threadIdx.x;
    const float* qr = g_q + (long)row * DD;
    qs[tid] = qr[tid];
    qs[tid + 128] = qr[tid + 128];
    __syncthreads();

    if (tid < 64) {
        float s = boff[tid];
#pragma unroll 8
        for (int k = 0; k < 256; k++) s = fmaf(qs[k], Woff[k * 64 + tid], s);
        g_off[(long)row * 64 + tid] = s;
    } else if (tid < 96) {
        int j = tid - 64;
        float s = battn[j];
#pragma unroll 8
        for (int k = 0; k < 256; k++) s = fmaf(qs[k], Wattn[k * 32 + j], s);
        lg[j] = s;
    }
    __syncthreads();

    if (tid < 32) {
        float x = lg[tid];
        float m = x;
        m = fmaxf(m, __shfl_xor_sync(0xffffffffu, m, 1));
        m = fmaxf(m, __shfl_xor_sync(0xffffffffu, m, 2));
        float e = expf(x - m);
        float s = e;
        s += __shfl_xor_sync(0xffffffffu, s, 1);
        s += __shfl_xor_sync(0xffffffffu, s, 2);
        g_aw[(long)row * 32 + tid] = e / s;
    }
}

// ---------------- Bezier + bilinear sampling + weighted sum ----------------
// one 256-thread block per (b,n).
// Phase 1: 320 items (8 heads x 10 bezier pts x 4 sample pts) -> 4 corners
//          (idx, weight) computed once, lane-parallel, into smem.
// Phase 2: warp = head, lane = channel; pure gather + FMA.
__global__ __launch_bounds__(256) void sample_kernel(
    const float* __restrict__ ctrl, const float* __restrict__ pc)
{
    __shared__ float s_ctrl[8];
    __shared__ float s_off[64];
    __shared__ float s_aw[32];
    __shared__ int   s_idx[320][4];
    __shared__ float s_w[320][4];

    const int bn = blockIdx.x;
    const int b = bn / NQ;
    const int tid = threadIdx.x;

    if (tid < 8)  s_ctrl[tid] = ctrl[(long)bn * 8 + tid];
    else if (tid >= 32 && tid < 96) s_off[tid - 32] = g_off[(long)bn * 64 + (tid - 32)];
    else if (tid >= 96 && tid < 128) s_aw[tid - 96] = g_aw[(long)bn * 32 + (tid - 96)];
    __syncthreads();

    const float p0 = pc[0], p1 = pc[1];
    const float invx = 1.f / (pc[3] - p0);
    const float invy = 1.f / (pc[4] - p1);

    for (int it = tid; it < 320; it += 256) {
        const int h = it / 40;
        const int kp = it - h * 40;
        const int k = kp >> 2;
        const int p = kp & 3;

        float t = (float)k * (1.0f / (NK - 1));
        float u = 1.f - t;
        float b0 = u * u * u, b1 = 3.f * u * u * t, b2 = 3.f * u * t * t, b3 = t * t * t;
        float px = b0 * s_ctrl[0] + b1 * s_ctrl[2] + b2 * s_ctrl[4] + b3 * s_ctrl[6];
        float py = b0 * s_ctrl[1] + b1 * s_ctrl[3] + b2 * s_ctrl[5] + b3 * s_ctrl[7];
        float nx = fminf(fmaxf((px - p0) * invx, 0.01f), 0.99f);
        float ny = fminf(fmaxf((py - p1) * invy, 0.01f), 0.99f);

        float gx = (nx + s_off[h * 8 + p * 2 + 0] * (1.f / WW)) * WW - 0.5f;
        float gy = (ny + s_off[h * 8 + p * 2 + 1] * (1.f / HH)) * HH - 0.5f;
        float fx = floorf(gx), fy = floorf(gy);
        float wx = gx - fx, wy = gy - fy;
        int xi = (int)fx, yi = (int)fy;
        float ap = s_aw[h * 4 + p];

#pragma unroll
        for (int c = 0; c < 4; c++) {
            int dx = c & 1, dy = c >> 1;
            int ix = xi + dx, iy = yi + dy;
            bool valid = (ix >= 0) & (ix < WW) & (iy >= 0) & (iy < HH);
            float wgt = valid ? ap * (dx ? wx : 1.f - wx) * (dy ? wy : 1.f - wy) : 0.f;
            int cx = min(max(ix, 0), WW - 1);
            int cy = min(max(iy, 0), HH - 1);
            s_w[it][c] = wgt;
            s_idx[it][c] = cy * WW + cx;
        }
    }
    __syncthreads();

    const int h = tid >> 5, lane = tid & 31;
    const float* vb = g_v + (long)b * HWSZ * DD + h * HDIM + lane;
    float acc = 0.f;
    const int base = h * 40;
#pragma unroll 4
    for (int i = 0; i < 40; i++) {
#pragma unroll
        for (int c = 0; c < 4; c++) {
            float w = s_w[base + i][c];
            int idx = s_idx[base + i][c];
            acc = fmaf(w, vb[(long)idx * DD], acc);
        }
    }
    g_s[(long)bn * DD + h * HDIM + lane] = acc;
}

// ---------------- launch ----------------
extern "C" void kernel_launch(void* const* d_in, const int* in_sizes, int n_in,
                              void* d_out, int out_size)
{
    const float* query = (const float*)d_in[0];
    const float* ctrl  = (const float*)d_in[1];
    const float* bev   = (const float*)d_in[2];
    const float* pc    = (const float*)d_in[4];
    const float* Wq    = (const float*)d_in[5];
    const float* bq    = (const float*)d_in[6];
    const float* Wv    = (const float*)d_in[7];
    const float* bv    = (const float*)d_in[8];
    const float* Woff  = (const float*)d_in[9];
    const float* boff  = (const float*)d_in[10];
    const float* Wattn = (const float*)d_in[11];
    const float* battn = (const float*)d_in[12];
    const float* Wmo   = (const float*)d_in[13];
    const float* bmo   = (const float*)d_in[14];
    const float* Wo    = (const float*)d_in[15];
    const float* bo    = (const float*)d_in[16];
    float* out = (float*)d_out;

    float *pq, *ps, *pt;
    cudaGetSymbolAddress((void**)&pq, g_q);
    cudaGetSymbolAddress((void**)&ps, g_s);
    cudaGetSymbolAddress((void**)&pt, g_t);

    cudaFuncSetAttribute(gemm_v, cudaFuncAttributeMaxDynamicSharedMemorySize, V_SMEM);
    cudaFuncSetAttribute(gemm_small<false>, cudaFuncAttributeMaxDynamicSharedMemorySize, S_SMEM);
    cudaFuncSetAttribute(gemm_small<true>, cudaFuncAttributeMaxDynamicSharedMemorySize, S_SMEM);

    const int Mq = BB * NQ;                     // 3600
    const dim3 sg_grid(2, (Mq + 63) / 64);      // 2 x 57

    // q = query @ Wq + bq
    gemm_small<false><<<sg_grid, 256, S_SMEM>>>(query, Wq, bq, nullptr, pq, Mq);

    // offsets + attention weights
    offattn_kernel<<<Mq, 128>>>(Woff, boff, Wattn, battn);

    // Wv -> WvT hi/lo (bf16 split)
    conv_wv<<<DD, 256>>>(Wv);

    // v = bev^T @ Wv + bv
    gemm_v<<<dim3(HWSZ / 64, BB), 256, V_SMEM>>>(bev, bv);

    // bezier + bilinear sampling + attention-weighted sum
    sample_kernel<<<BB * NQ, 256>>>(ctrl, pc);

    // t = s @ Wmo + bmo + q
    gemm_small<true><<<sg_grid, 256, S_SMEM>>>(ps, Wmo, bmo, pq, pt, Mq);

    // out = t @ Wo + bo
    gemm_small<false><<<sg_grid, 256, S_SMEM>>>(pt, Wo, bo, nullptr, out, Mq);
}